// round 1
// baseline (speedup 1.0000x reference)
#include <cuda_runtime.h>
#include <math.h>

#define BB 4
#define SS 2048
#define DD 768
#define HH 12
#define DKK 64
#define MTOT (BB*SS)   // 8192
#define NQKV (3*DD)    // 2304

// Scratch: qkv in [t][b][h][s][dk] layout, and attention output in [b][s][d] layout.
__device__ float g_qkv[(size_t)3 * BB * HH * SS * DKK];   // 18.87M floats
__device__ float g_obuf[(size_t)BB * SS * DD];            // 6.29M floats

// ---------------------------------------------------------------------------
// GEMM: C = A(M,K) @ W(N,K)^T, fp32, 128x128 block tile, BK=8, 8x8 per thread.
// REMAP==1: scatter into g_qkv [t][b][h][s][dk]; REMAP==0: plain row-major C.
// ---------------------------------------------------------------------------
template <int REMAP>
__global__ __launch_bounds__(256) void gemm_tn(const float* __restrict__ A,
                                               const float* __restrict__ W,
                                               float* __restrict__ C,
                                               int M, int N, int K) {
    __shared__ float As[8][128];
    __shared__ float Bs[8][128];

    const int tid = threadIdx.x;
    const int tx = tid & 15;        // 0..15  -> n microtile
    const int ty = tid >> 4;        // 0..15  -> m microtile
    const int m0 = blockIdx.y * 128;
    const int n0 = blockIdx.x * 128;

    const int lrow = tid >> 1;          // 0..127
    const int lkv  = (tid & 1) * 4;     // 0 or 4

    const float* Ag = A + (size_t)(m0 + lrow) * K + lkv;
    const float* Wg = W + (size_t)(n0 + lrow) * K + lkv;

    float acc[8][8];
#pragma unroll
    for (int i = 0; i < 8; i++)
#pragma unroll
        for (int j = 0; j < 8; j++) acc[i][j] = 0.0f;

    for (int k0 = 0; k0 < K; k0 += 8) {
        float4 av = *(const float4*)(Ag + k0);
        float4 wv = *(const float4*)(Wg + k0);
        As[lkv + 0][lrow] = av.x;
        As[lkv + 1][lrow] = av.y;
        As[lkv + 2][lrow] = av.z;
        As[lkv + 3][lrow] = av.w;
        Bs[lkv + 0][lrow] = wv.x;
        Bs[lkv + 1][lrow] = wv.y;
        Bs[lkv + 2][lrow] = wv.z;
        Bs[lkv + 3][lrow] = wv.w;
        __syncthreads();

#pragma unroll
        for (int kk = 0; kk < 8; kk++) {
            float af[8], bf[8];
#pragma unroll
            for (int i = 0; i < 8; i++) af[i] = As[kk][ty * 8 + i];
#pragma unroll
            for (int j = 0; j < 8; j++) bf[j] = Bs[kk][tx * 8 + j];
#pragma unroll
            for (int i = 0; i < 8; i++)
#pragma unroll
                for (int j = 0; j < 8; j++) acc[i][j] = fmaf(af[i], bf[j], acc[i][j]);
        }
        __syncthreads();
    }

#pragma unroll
    for (int i = 0; i < 8; i++) {
        const int m = m0 + ty * 8 + i;
#pragma unroll
        for (int j = 0; j < 8; j++) {
            const int n = n0 + tx * 8 + j;
            if (REMAP) {
                // n -> (t, h, e); m -> (b, s); store to g_qkv[t][b][h][s][dk]
                const int t = n / DD;
                const int r = n - t * DD;
                const int h = r >> 6;
                const int e = r & 63;
                const int b = m >> 11;
                const int s = m & 2047;
                size_t idx = ((((size_t)t * BB + b) * HH + h) * SS + s) * DKK + e;
                g_qkv[idx] = acc[i][j];
            } else {
                C[(size_t)m * N + n] = acc[i][j];
            }
        }
    }
}

// ---------------------------------------------------------------------------
// Flash-style causal attention. One CTA per (q-tile of 64, head, batch).
// 16x16 threads, 4x4 microtiles. Online softmax. 48KB static smem exactly.
// Transposed tiles use an XOR swizzle to avoid 16/32-way transpose conflicts.
// ---------------------------------------------------------------------------
__device__ __forceinline__ int SW(int maj, int mn) {
    return (maj << 6) + (mn ^ (maj & 31));
}

__global__ __launch_bounds__(256) void attn_kernel() {
    __shared__ float Qs[64 * 64];   // transposed+swizzled: Qs[SW(e, row)]
    __shared__ float KVs[64 * 64];  // K: transposed+swizzled; V: natural [j][n]
    __shared__ float Ps[64 * 64];   // transposed+swizzled: Ps[SW(j, i)]

    const int qt = blockIdx.x;   // q tile (0..31)
    const int h  = blockIdx.y;
    const int b  = blockIdx.z;
    const int tid = threadIdx.x;
    const int tx = tid & 15;     // -> k-col / dk-col microtile
    const int ty = tid >> 4;     // -> q-row microtile

    const size_t bh = (size_t)b * HH + h;
    const size_t plane = (size_t)BB * HH * SS * DKK;
    const float* Qg = g_qkv + 0 * plane + bh * SS * DKK;
    const float* Kg = g_qkv + 1 * plane + bh * SS * DKK;
    const float* Vg = g_qkv + 2 * plane + bh * SS * DKK;

    // Load Q tile (rows qt*64..qt*64+63), transposed into Qs.
    {
        const int cvec = (tid & 15) * 4;
        const int rr = tid >> 4;
#pragma unroll
        for (int it = 0; it < 4; it++) {
            const int row = rr + it * 16;
            float4 v = *(const float4*)(Qg + (size_t)(qt * 64 + row) * DKK + cvec);
            Qs[SW(cvec + 0, row)] = v.x;
            Qs[SW(cvec + 1, row)] = v.y;
            Qs[SW(cvec + 2, row)] = v.z;
            Qs[SW(cvec + 3, row)] = v.w;
        }
    }

    float m_run[4], l_run[4], o_acc[4][4];
#pragma unroll
    for (int i = 0; i < 4; i++) {
        m_run[i] = -INFINITY;
        l_run[i] = 0.0f;
#pragma unroll
        for (int j = 0; j < 4; j++) o_acc[i][j] = 0.0f;
    }
    __syncthreads();

    for (int kt = 0; kt <= qt; kt++) {
        // Load K tile transposed into KVs.
        {
            const int cvec = (tid & 15) * 4;
            const int rr = tid >> 4;
#pragma unroll
            for (int it = 0; it < 4; it++) {
                const int row = rr + it * 16;
                float4 v = *(const float4*)(Kg + (size_t)(kt * 64 + row) * DKK + cvec);
                KVs[SW(cvec + 0, row)] = v.x;
                KVs[SW(cvec + 1, row)] = v.y;
                KVs[SW(cvec + 2, row)] = v.z;
                KVs[SW(cvec + 3, row)] = v.w;
            }
        }
        __syncthreads();

        // S = (Q K^T) * 1/sqrt(dk)
        float s[4][4];
#pragma unroll
        for (int i = 0; i < 4; i++)
#pragma unroll
            for (int j = 0; j < 4; j++) s[i][j] = 0.0f;

#pragma unroll 4
        for (int e = 0; e < 64; e++) {
            float af[4], bf[4];
#pragma unroll
            for (int i = 0; i < 4; i++) af[i] = Qs[SW(e, ty * 4 + i)];
#pragma unroll
            for (int j = 0; j < 4; j++) bf[j] = KVs[SW(e, tx * 4 + j)];
#pragma unroll
            for (int i = 0; i < 4; i++)
#pragma unroll
                for (int j = 0; j < 4; j++) s[i][j] = fmaf(af[i], bf[j], s[i][j]);
        }

        // scale + causal mask (only the diagonal tile needs masking)
#pragma unroll
        for (int i = 0; i < 4; i++)
#pragma unroll
            for (int j = 0; j < 4; j++) s[i][j] *= 0.125f;

        if (kt == qt) {
#pragma unroll
            for (int i = 0; i < 4; i++) {
                const int qg = ty * 4 + i;
#pragma unroll
                for (int j = 0; j < 4; j++) {
                    const int kg = tx * 4 + j;
                    if (kg > qg) s[i][j] = -INFINITY;
                }
            }
        }

        // Online softmax update
        float m_new[4], scal[4], rsum[4];
#pragma unroll
        for (int i = 0; i < 4; i++) {
            float mv = fmaxf(fmaxf(s[i][0], s[i][1]), fmaxf(s[i][2], s[i][3]));
#pragma unroll
            for (int off = 8; off >= 1; off >>= 1)
                mv = fmaxf(mv, __shfl_xor_sync(0xffffffffu, mv, off));
            m_new[i] = fmaxf(m_run[i], mv);
            scal[i] = __expf(m_run[i] - m_new[i]);
        }

#pragma unroll
        for (int i = 0; i < 4; i++) {
            float rs = 0.0f;
#pragma unroll
            for (int j = 0; j < 4; j++) {
                s[i][j] = __expf(s[i][j] - m_new[i]);
                rs += s[i][j];
            }
#pragma unroll
            for (int off = 8; off >= 1; off >>= 1)
                rs += __shfl_xor_sync(0xffffffffu, rs, off);
            rsum[i] = rs;
        }

#pragma unroll
        for (int i = 0; i < 4; i++) {
            l_run[i] = l_run[i] * scal[i] + rsum[i];
            m_run[i] = m_new[i];
#pragma unroll
            for (int j = 0; j < 4; j++) o_acc[i][j] *= scal[i];
        }

        // Store P transposed (Ps[j][i]) for the PV GEMM
#pragma unroll
        for (int i = 0; i < 4; i++)
#pragma unroll
            for (int j = 0; j < 4; j++)
                Ps[SW(tx * 4 + j, ty * 4 + i)] = s[i][j];
        __syncthreads();  // P visible; everyone done reading K tile

        // Load V tile (natural layout) into KVs
        {
            const int cvec = (tid & 15) * 4;
            const int rr = tid >> 4;
#pragma unroll
            for (int it = 0; it < 4; it++) {
                const int row = rr + it * 16;
                float4 v = *(const float4*)(Vg + (size_t)(kt * 64 + row) * DKK + cvec);
                *(float4*)&KVs[row * 64 + cvec] = v;
            }
        }
        __syncthreads();

        // O += P @ V
#pragma unroll 4
        for (int j = 0; j < 64; j++) {
            float pa[4], vb[4];
#pragma unroll
            for (int i = 0; i < 4; i++) pa[i] = Ps[SW(j, ty * 4 + i)];
#pragma unroll
            for (int n = 0; n < 4; n++) vb[n] = KVs[j * 64 + tx * 4 + n];
#pragma unroll
            for (int i = 0; i < 4; i++)
#pragma unroll
                for (int n = 0; n < 4; n++) o_acc[i][n] = fmaf(pa[i], vb[n], o_acc[i][n]);
        }
        __syncthreads();  // done with Ps / KVs before next iteration
    }

    // Epilogue: normalize and write to g_obuf[b][s][d], d = h*64 + col
#pragma unroll
    for (int i = 0; i < 4; i++) {
        const float inv = 1.0f / l_run[i];
        const int srow = qt * 64 + ty * 4 + i;
#pragma unroll
        for (int j = 0; j < 4; j++) {
            const int col = tx * 4 + j;
            g_obuf[((size_t)b * SS + srow) * DD + h * 64 + col] = o_acc[i][j] * inv;
        }
    }
}

// ---------------------------------------------------------------------------
extern "C" void kernel_launch(void* const* d_in, const int* in_sizes, int n_in,
                              void* d_out, int out_size) {
    const float* x   = (const float*)d_in[0];  // (4, 2048, 768)
    const float* wqk = (const float*)d_in[1];  // (3, 768, 768)
    const float* wo  = (const float*)d_in[2];  // (768, 768)
    float* out = (float*)d_out;                // (4, 2048, 768)

    float* qkv_dummy = nullptr;  // REMAP==1 writes g_qkv directly
    (void)in_sizes; (void)n_in; (void)out_size;

    // 1) Fused QKV projection: (8192 x 768) @ (2304 x 768)^T -> g_qkv
    {
        dim3 grid(NQKV / 128, MTOT / 128);
        gemm_tn<1><<<grid, 256>>>(x, wqk, qkv_dummy, MTOT, NQKV, DD);
    }

    // 2) Causal attention -> g_obuf
    {
        dim3 grid(SS / 64, HH, BB);
        attn_kernel<<<grid, 256>>>();
    }

    // 3) O projection: (8192 x 768) @ (768 x 768)^T -> out
    {
        float* obuf_ptr;
        cudaGetSymbolAddress((void**)&obuf_ptr, g_obuf);
        dim3 grid(DD / 128, MTOT / 128);
        gemm_tn<0><<<grid, 256>>>(obuf_ptr, wo, out, MTOT, DD, DD);
    }
}

// round 3
// speedup vs baseline: 3.3184x; 3.3184x over previous
#include <cuda_runtime.h>
#include <math.h>
#include <stdint.h>

#define BB 4
#define SS 2048
#define DD 768
#define HH 12
#define DKK 64
#define MTOT (BB*SS)   // 8192
#define NQKV (3*DD)    // 2304

// Scratch
__device__ float g_qkv[(size_t)3 * BB * HH * SS * DKK];
__device__ float g_obuf[(size_t)BB * SS * DD];

// ---------------------------------------------------------------------------
// helpers
// ---------------------------------------------------------------------------
__device__ __forceinline__ uint32_t f2tf(float x) {
    uint32_t r;
    asm("cvt.rna.tf32.f32 %0, %1;" : "=r"(r) : "f"(x));
    return r;
}

__device__ __forceinline__ void mma_tf32(float* c, const uint32_t* a, const uint32_t* b) {
    asm volatile(
        "mma.sync.aligned.m16n8k8.row.col.f32.tf32.tf32.f32 "
        "{%0,%1,%2,%3}, {%4,%5,%6,%7}, {%8,%9}, {%0,%1,%2,%3};\n"
        : "+f"(c[0]), "+f"(c[1]), "+f"(c[2]), "+f"(c[3])
        : "r"(a[0]), "r"(a[1]), "r"(a[2]), "r"(a[3]), "r"(b[0]), "r"(b[1]));
}

// fast 2^x on the FMA/ALU pipes (no MUFU).
__device__ __forceinline__ float fexp2(float x) {
    x = fmaxf(x, -120.0f);
    float z = x + 12582912.0f;                 // round-to-nearest-int trick
    float f = x - (z - 12582912.0f);           // f in [-0.5, 0.5]
    int   i = __float_as_int(z) - 0x4B400000;  // integer part
    float p = 0.0096818f;
    p = fmaf(p, f, 0.0555041f);
    p = fmaf(p, f, 0.2402265f);
    p = fmaf(p, f, 0.6931472f);
    p = fmaf(p, f, 1.0f);
    return __int_as_float(__float_as_int(p) + (i << 23));
}

#define CEXP 0.1803368801111204f   /* log2(e)/sqrt(64) */
#define NEGINF __int_as_float(0xff800000)

// ---------------------------------------------------------------------------
// tf32 tensor-core GEMM: C = A(M,K) @ W(N,K)^T
// BM=BN=128, BK=16, 256 thr (8 warps, 2x4), warp tile 64x32, double-buffered.
// REMAP==1: scatter into g_qkv [t][b][h][s][dk].
// ---------------------------------------------------------------------------
template <int REMAP>
__global__ __launch_bounds__(256) void gemm_tf32(const float* __restrict__ A,
                                                 const float* __restrict__ W,
                                                 float* __restrict__ C,
                                                 int M, int N, int K) {
    __shared__ uint32_t As[2][128 * 20];
    __shared__ uint32_t Bs[2][128 * 20];

    const int tid  = threadIdx.x;
    const int lane = tid & 31;
    const int wid  = tid >> 5;
    const int wm   = wid >> 2;      // 0..1
    const int wn   = wid & 3;       // 0..3
    const int m0   = blockIdx.y * 128;
    const int n0   = blockIdx.x * 128;

    const int r0 = tid >> 2;            // 0..63 (rows r0 and r0+64)
    const int kv = (tid & 3) << 2;      // 0,4,8,12

    const int NT = K / 16;

    float4 areg[2], breg[2];
    const float* Abase = A + (size_t)(m0 + r0) * K + kv;
    const float* Wbase = W + (size_t)(n0 + r0) * K + kv;

    float c[4][4][4];
#pragma unroll
    for (int mt = 0; mt < 4; mt++)
#pragma unroll
        for (int nt = 0; nt < 4; nt++)
#pragma unroll
            for (int j = 0; j < 4; j++) c[mt][nt][j] = 0.0f;

    areg[0] = *(const float4*)(Abase);
    areg[1] = *(const float4*)(Abase + (size_t)64 * K);
    breg[0] = *(const float4*)(Wbase);
    breg[1] = *(const float4*)(Wbase + (size_t)64 * K);
    {
        uint4 u;
        u.x = f2tf(areg[0].x); u.y = f2tf(areg[0].y); u.z = f2tf(areg[0].z); u.w = f2tf(areg[0].w);
        *(uint4*)&As[0][r0 * 20 + kv] = u;
        u.x = f2tf(areg[1].x); u.y = f2tf(areg[1].y); u.z = f2tf(areg[1].z); u.w = f2tf(areg[1].w);
        *(uint4*)&As[0][(r0 + 64) * 20 + kv] = u;
        u.x = f2tf(breg[0].x); u.y = f2tf(breg[0].y); u.z = f2tf(breg[0].z); u.w = f2tf(breg[0].w);
        *(uint4*)&Bs[0][r0 * 20 + kv] = u;
        u.x = f2tf(breg[1].x); u.y = f2tf(breg[1].y); u.z = f2tf(breg[1].z); u.w = f2tf(breg[1].w);
        *(uint4*)&Bs[0][(r0 + 64) * 20 + kv] = u;
    }
    __syncthreads();

    for (int kt = 0; kt < NT; kt++) {
        const int buf = kt & 1;
        const bool more = (kt + 1 < NT);
        if (more) {
            const float* Ap = Abase + (size_t)(kt + 1) * 16;
            const float* Wp = Wbase + (size_t)(kt + 1) * 16;
            areg[0] = *(const float4*)(Ap);
            areg[1] = *(const float4*)(Ap + (size_t)64 * K);
            breg[0] = *(const float4*)(Wp);
            breg[1] = *(const float4*)(Wp + (size_t)64 * K);
        }

#pragma unroll
        for (int k0 = 0; k0 < 16; k0 += 8) {
            uint32_t af[4][4];
#pragma unroll
            for (int mt = 0; mt < 4; mt++) {
                const int row = wm * 64 + mt * 16 + (lane >> 2);
                af[mt][0] = As[buf][row * 20 + k0 + (lane & 3)];
                af[mt][1] = As[buf][(row + 8) * 20 + k0 + (lane & 3)];
                af[mt][2] = As[buf][row * 20 + k0 + 4 + (lane & 3)];
                af[mt][3] = As[buf][(row + 8) * 20 + k0 + 4 + (lane & 3)];
            }
            uint32_t bf[4][2];
#pragma unroll
            for (int nt = 0; nt < 4; nt++) {
                const int col = wn * 32 + nt * 8 + (lane >> 2);
                bf[nt][0] = Bs[buf][col * 20 + k0 + (lane & 3)];
                bf[nt][1] = Bs[buf][col * 20 + k0 + 4 + (lane & 3)];
            }
#pragma unroll
            for (int mt = 0; mt < 4; mt++)
#pragma unroll
                for (int nt = 0; nt < 4; nt++)
                    mma_tf32(c[mt][nt], af[mt], bf[nt]);
        }

        if (more) {
            const int nb = (kt + 1) & 1;
            uint4 u;
            u.x = f2tf(areg[0].x); u.y = f2tf(areg[0].y); u.z = f2tf(areg[0].z); u.w = f2tf(areg[0].w);
            *(uint4*)&As[nb][r0 * 20 + kv] = u;
            u.x = f2tf(areg[1].x); u.y = f2tf(areg[1].y); u.z = f2tf(areg[1].z); u.w = f2tf(areg[1].w);
            *(uint4*)&As[nb][(r0 + 64) * 20 + kv] = u;
            u.x = f2tf(breg[0].x); u.y = f2tf(breg[0].y); u.z = f2tf(breg[0].z); u.w = f2tf(breg[0].w);
            *(uint4*)&Bs[nb][r0 * 20 + kv] = u;
            u.x = f2tf(breg[1].x); u.y = f2tf(breg[1].y); u.z = f2tf(breg[1].z); u.w = f2tf(breg[1].w);
            *(uint4*)&Bs[nb][(r0 + 64) * 20 + kv] = u;
        }
        __syncthreads();
    }

#pragma unroll
    for (int mt = 0; mt < 4; mt++) {
#pragma unroll
        for (int half = 0; half < 2; half++) {
            const int m = m0 + wm * 64 + mt * 16 + (lane >> 2) + half * 8;
#pragma unroll
            for (int nt = 0; nt < 4; nt++) {
                const int n = n0 + wn * 32 + nt * 8 + 2 * (lane & 3);
                const float v0 = c[mt][nt][2 * half + 0];
                const float v1 = c[mt][nt][2 * half + 1];
                if (REMAP) {
#pragma unroll
                    for (int j = 0; j < 2; j++) {
                        const int nn = n + j;
                        const int t = nn / DD;
                        const int r = nn - t * DD;
                        const int hh = r >> 6;
                        const int e = r & 63;
                        const int bb = m >> 11;
                        const int ss = m & 2047;
                        size_t idx = ((((size_t)t * BB + bb) * HH + hh) * SS + ss) * DKK + e;
                        g_qkv[idx] = j ? v1 : v0;
                    }
                } else {
                    float2 v = make_float2(v0, v1);
                    *(float2*)&C[(size_t)m * N + n] = v;
                }
            }
        }
    }
}

// ---------------------------------------------------------------------------
// Tensor-core causal flash attention. Br=128, Bc=64, dk=64.
// 256 threads = 8 warps; EACH WARP OWNS 16 FULL ROWS (16 x 64 warp tile),
// so the online-softmax row reduction is entirely intra-warp (quad shuffle).
// Dynamic smem: Qs 128x68 + KVs 64x68 + Ps 128x68 (tf32 words) = 87040 B.
// ---------------------------------------------------------------------------
__global__ __launch_bounds__(256) void attn_tc() {
    extern __shared__ uint32_t smx[];
    uint32_t* Qs  = smx;                       // [128][68]
    uint32_t* KVs = smx + 128 * 68;            // [64][68]
    uint32_t* Ps  = smx + 128 * 68 + 64 * 68;  // [128][68]

    const int qt = blockIdx.x;   // 0..15 (128-row q blocks)
    const int h  = blockIdx.y;
    const int b  = blockIdx.z;
    const int tid  = threadIdx.x;
    const int lane = tid & 31;
    const int wm   = tid >> 5;   // 0..7  -> 16-row slice

    const size_t plane = (size_t)BB * HH * SS * DKK;
    const size_t bh = (size_t)b * HH + h;
    const float* Qg = g_qkv + 0 * plane + bh * SS * DKK;
    const float* Kg = g_qkv + 1 * plane + bh * SS * DKK;
    const float* Vg = g_qkv + 2 * plane + bh * SS * DKK;

    // load Q tile (128 x 64) -> tf32 smem
#pragma unroll
    for (int i = 0; i < 8; i++) {
        const int idx = tid + i * 256;
        const int row = idx >> 4;
        const int c4  = (idx & 15) << 2;
        float4 v = *(const float4*)(Qg + ((size_t)(qt * 128 + row) << 6) + c4);
        uint4 u;
        u.x = f2tf(v.x); u.y = f2tf(v.y); u.z = f2tf(v.z); u.w = f2tf(v.w);
        *(uint4*)&Qs[row * 68 + c4] = u;
    }

    float m_run[2], l_run[2], o[8][4];
    m_run[0] = NEGINF; m_run[1] = NEGINF;
    l_run[0] = 0.0f;   l_run[1] = 0.0f;
#pragma unroll
    for (int nt = 0; nt < 8; nt++)
#pragma unroll
        for (int j = 0; j < 4; j++) o[nt][j] = 0.0f;

    __syncthreads();

    const int ktmax = 2 * qt + 1;
    for (int kt = 0; kt <= ktmax; kt++) {
        // K tile -> KVs
#pragma unroll
        for (int i = 0; i < 4; i++) {
            const int idx = tid + i * 256;
            const int row = idx >> 4;
            const int c4  = (idx & 15) << 2;
            float4 v = *(const float4*)(Kg + ((size_t)(kt * 64 + row) << 6) + c4);
            uint4 u;
            u.x = f2tf(v.x); u.y = f2tf(v.y); u.z = f2tf(v.z); u.w = f2tf(v.w);
            *(uint4*)&KVs[row * 68 + c4] = u;
        }
        __syncthreads();

        // S = Q K^T : warp computes 16 x 64
        float s[8][4];
#pragma unroll
        for (int nt = 0; nt < 8; nt++)
#pragma unroll
            for (int j = 0; j < 4; j++) s[nt][j] = 0.0f;

#pragma unroll
        for (int k0 = 0; k0 < 64; k0 += 8) {
            uint32_t af[4];
            const int row = wm * 16 + (lane >> 2);
            af[0] = Qs[row * 68 + k0 + (lane & 3)];
            af[1] = Qs[(row + 8) * 68 + k0 + (lane & 3)];
            af[2] = Qs[row * 68 + k0 + 4 + (lane & 3)];
            af[3] = Qs[(row + 8) * 68 + k0 + 4 + (lane & 3)];
            uint32_t bf[8][2];
#pragma unroll
            for (int nt = 0; nt < 8; nt++) {
                const int col = nt * 8 + (lane >> 2);
                bf[nt][0] = KVs[col * 68 + k0 + (lane & 3)];
                bf[nt][1] = KVs[col * 68 + k0 + 4 + (lane & 3)];
            }
#pragma unroll
            for (int nt = 0; nt < 8; nt++)
                mma_tf32(s[nt], af, bf[nt]);
        }

        // causal mask (only diagonal-adjacent tiles)
        if (kt >= 2 * qt) {
#pragma unroll
            for (int cc = 0; cc < 4; cc++) {
                const int row_g = qt * 128 + wm * 16 + (lane >> 2) + 8 * (cc >> 1);
#pragma unroll
                for (int nt = 0; nt < 8; nt++) {
                    const int col_g = kt * 64 + nt * 8 + 2 * (lane & 3) + (cc & 1);
                    if (col_g > row_g) s[nt][cc] = NEGINF;
                }
            }
        }

        // online softmax: each warp owns full rows, reduce across the 4-lane quad
#pragma unroll
        for (int half = 0; half < 2; half++) {
            float mv = NEGINF;
#pragma unroll
            for (int nt = 0; nt < 8; nt++)
                mv = fmaxf(mv, fmaxf(s[nt][2 * half], s[nt][2 * half + 1]));
            mv = fmaxf(mv, __shfl_xor_sync(0xffffffffu, mv, 1));
            mv = fmaxf(mv, __shfl_xor_sync(0xffffffffu, mv, 2));
            const float mn = fmaxf(m_run[half], mv);
            const float sc = fexp2((m_run[half] - mn) * CEXP);
            m_run[half] = mn;
            float rs = 0.0f;
#pragma unroll
            for (int nt = 0; nt < 8; nt++)
#pragma unroll
                for (int j = 0; j < 2; j++) {
                    float p = fexp2((s[nt][2 * half + j] - mn) * CEXP);
                    s[nt][2 * half + j] = p;
                    rs += p;
                }
            rs += __shfl_xor_sync(0xffffffffu, rs, 1);
            rs += __shfl_xor_sync(0xffffffffu, rs, 2);
            l_run[half] = l_run[half] * sc + rs;
#pragma unroll
            for (int nt = 0; nt < 8; nt++)
#pragma unroll
                for (int j = 0; j < 2; j++) o[nt][2 * half + j] *= sc;
        }

        // write P (tf32) to smem
#pragma unroll
        for (int half = 0; half < 2; half++) {
            const int row = wm * 16 + (lane >> 2) + 8 * half;
#pragma unroll
            for (int nt = 0; nt < 8; nt++) {
                const int col = nt * 8 + 2 * (lane & 3);
                uint2 u;
                u.x = f2tf(s[nt][2 * half]);
                u.y = f2tf(s[nt][2 * half + 1]);
                *(uint2*)&Ps[row * 68 + col] = u;
            }
        }
        __syncthreads();   // P visible; all S-mma reads of K done

        // V tile -> KVs
#pragma unroll
        for (int i = 0; i < 4; i++) {
            const int idx = tid + i * 256;
            const int row = idx >> 4;
            const int c4  = (idx & 15) << 2;
            float4 v = *(const float4*)(Vg + ((size_t)(kt * 64 + row) << 6) + c4);
            uint4 u;
            u.x = f2tf(v.x); u.y = f2tf(v.y); u.z = f2tf(v.z); u.w = f2tf(v.w);
            *(uint4*)&KVs[row * 68 + c4] = u;
        }
        __syncthreads();

        // O += P @ V   (V natural layout: KVs[k][n])
#pragma unroll
        for (int k0 = 0; k0 < 64; k0 += 8) {
            uint32_t af[4];
            const int row = wm * 16 + (lane >> 2);
            af[0] = Ps[row * 68 + k0 + (lane & 3)];
            af[1] = Ps[(row + 8) * 68 + k0 + (lane & 3)];
            af[2] = Ps[row * 68 + k0 + 4 + (lane & 3)];
            af[3] = Ps[(row + 8) * 68 + k0 + 4 + (lane & 3)];
            uint32_t bf[8][2];
#pragma unroll
            for (int nt = 0; nt < 8; nt++) {
                const int col = nt * 8 + (lane >> 2);
                bf[nt][0] = KVs[(k0 + (lane & 3)) * 68 + col];
                bf[nt][1] = KVs[(k0 + 4 + (lane & 3)) * 68 + col];
            }
#pragma unroll
            for (int nt = 0; nt < 8; nt++)
                mma_tf32(o[nt], af, bf[nt]);
        }
        __syncthreads();   // KVs/Ps free for next iteration
    }

    // epilogue: normalize, write g_obuf[b][s][d]
#pragma unroll
    for (int half = 0; half < 2; half++) {
        const float inv = 1.0f / l_run[half];
        const int row = qt * 128 + wm * 16 + (lane >> 2) + 8 * half;
#pragma unroll
        for (int nt = 0; nt < 8; nt++) {
            const int d = h * 64 + nt * 8 + 2 * (lane & 3);
            float2 v = make_float2(o[nt][2 * half] * inv,
                                   o[nt][2 * half + 1] * inv);
            *(float2*)&g_obuf[((size_t)b * SS + row) * DD + d] = v;
        }
    }
}

#define ATTN_SMEM (320 * 68 * 4)

// ---------------------------------------------------------------------------
extern "C" void kernel_launch(void* const* d_in, const int* in_sizes, int n_in,
                              void* d_out, int out_size) {
    const float* x   = (const float*)d_in[0];  // (4, 2048, 768)
    const float* wqk = (const float*)d_in[1];  // (3, 768, 768)
    const float* wo  = (const float*)d_in[2];  // (768, 768)
    float* out = (float*)d_out;                // (4, 2048, 768)
    (void)in_sizes; (void)n_in; (void)out_size;

    cudaFuncSetAttribute(attn_tc, cudaFuncAttributeMaxDynamicSharedMemorySize, ATTN_SMEM);

    // 1) QKV projection: (8192 x 768) @ (2304 x 768)^T -> g_qkv (remapped)
    gemm_tf32<1><<<dim3(NQKV / 128, MTOT / 128), 256>>>(x, wqk, nullptr, MTOT, NQKV, DD);

    // 2) Causal attention -> g_obuf
    attn_tc<<<dim3(SS / 128, HH, BB), 256, ATTN_SMEM>>>();

    // 3) O projection -> out
    float* obuf_ptr;
    cudaGetSymbolAddress((void**)&obuf_ptr, g_obuf);
    gemm_tf32<0><<<dim3(DD / 128, MTOT / 128), 256>>>(obuf_ptr, wo, out, MTOT, DD, DD);
}

// round 4
// speedup vs baseline: 3.7562x; 1.1319x over previous
#include <cuda_runtime.h>
#include <math.h>
#include <stdint.h>

#define BB 4
#define SS 2048
#define DD 768
#define HH 12
#define DKK 64
#define MTOT (BB*SS)   // 8192
#define NQKV (3*DD)    // 2304

// Scratch
__device__ float g_qkv[(size_t)3 * BB * HH * SS * DKK];
__device__ float g_obuf[(size_t)BB * SS * DD];

// ---------------------------------------------------------------------------
// helpers
// ---------------------------------------------------------------------------
__device__ __forceinline__ uint32_t f2tf(float x) {
    uint32_t r;
    asm("cvt.rna.tf32.f32 %0, %1;" : "=r"(r) : "f"(x));
    return r;
}

__device__ __forceinline__ void mma_tf32(float* c, const uint32_t* a, const uint32_t* b) {
    asm volatile(
        "mma.sync.aligned.m16n8k8.row.col.f32.tf32.tf32.f32 "
        "{%0,%1,%2,%3}, {%4,%5,%6,%7}, {%8,%9}, {%0,%1,%2,%3};\n"
        : "+f"(c[0]), "+f"(c[1]), "+f"(c[2]), "+f"(c[3])
        : "r"(a[0]), "r"(a[1]), "r"(a[2]), "r"(a[3]), "r"(b[0]), "r"(b[1]));
}

__device__ __forceinline__ void cp_async16(void* smem, const void* gmem) {
    uint32_t s = (uint32_t)__cvta_generic_to_shared(smem);
    asm volatile("cp.async.cg.shared.global [%0], [%1], 16;\n" :: "r"(s), "l"(gmem));
}
__device__ __forceinline__ void cp_commit() { asm volatile("cp.async.commit_group;\n"); }
template <int N>
__device__ __forceinline__ void cp_wait() { asm volatile("cp.async.wait_group %0;\n" :: "n"(N)); }

// fast 2^x on the FMA/ALU pipes (no MUFU).
__device__ __forceinline__ float fexp2(float x) {
    x = fmaxf(x, -120.0f);
    float z = x + 12582912.0f;
    float f = x - (z - 12582912.0f);
    int   i = __float_as_int(z) - 0x4B400000;
    float p = 0.0096818f;
    p = fmaf(p, f, 0.0555041f);
    p = fmaf(p, f, 0.2402265f);
    p = fmaf(p, f, 0.6931472f);
    p = fmaf(p, f, 1.0f);
    return __int_as_float(__float_as_int(p) + (i << 23));
}

#define CEXP 0.1803368801111204f   /* log2(e)/sqrt(64) */
#define NEGINF __int_as_float(0xff800000)

// ---------------------------------------------------------------------------
// tf32 tensor-core GEMM: C = A(M,K) @ W(N,K)^T
// BM=BN=128, BK=16, 256 thr (8 warps, 2x4), warp tile 64x32.
// 3-stage cp.async pipeline, raw fp32 in smem, cvt.rna at fragment load.
// REMAP==1: scatter into g_qkv [t][b][h][s][dk].
// ---------------------------------------------------------------------------
#define GSTAGES 3
#define GSLOT (128 * 20)
#define GEMM_SMEM (GSTAGES * GSLOT * 2 * 4)

template <int REMAP>
__global__ __launch_bounds__(256, 2) void gemm_tf32(const float* __restrict__ A,
                                                    const float* __restrict__ W,
                                                    float* __restrict__ C,
                                                    int M, int N, int K) {
    extern __shared__ float gsm[];
    float* As = gsm;                      // [GSTAGES][128*20]
    float* Bs = gsm + GSTAGES * GSLOT;

    const int tid  = threadIdx.x;
    const int lane = tid & 31;
    const int wid  = tid >> 5;
    const int wm   = wid >> 2;      // 0..1
    const int wn   = wid & 3;       // 0..3
    const int m0   = blockIdx.y * 128;
    const int n0   = blockIdx.x * 128;

    const int r0 = tid >> 2;            // 0..63 (rows r0 and r0+64)
    const int kv = (tid & 3) << 2;      // 0,4,8,12

    const int NT = K / 16;

    const float* Abase = A + (size_t)(m0 + r0) * K + kv;
    const float* Wbase = W + (size_t)(n0 + r0) * K + kv;

    float c[4][4][4];
#pragma unroll
    for (int mt = 0; mt < 4; mt++)
#pragma unroll
        for (int nt = 0; nt < 4; nt++)
#pragma unroll
            for (int j = 0; j < 4; j++) c[mt][nt][j] = 0.0f;

    // prologue: issue first GSTAGES-1 stages
#pragma unroll
    for (int s = 0; s < GSTAGES - 1; s++) {
        float* as = As + s * GSLOT;
        float* bs = Bs + s * GSLOT;
        const float* ap = Abase + s * 16;
        const float* wp = Wbase + s * 16;
        cp_async16(&as[r0 * 20 + kv], ap);
        cp_async16(&as[(r0 + 64) * 20 + kv], ap + (size_t)64 * K);
        cp_async16(&bs[r0 * 20 + kv], wp);
        cp_async16(&bs[(r0 + 64) * 20 + kv], wp + (size_t)64 * K);
        cp_commit();
    }

    for (int kt = 0; kt < NT; kt++) {
        cp_wait<GSTAGES - 2>();
        __syncthreads();

        // issue stage kt+GSTAGES-1 (overwrites slot of stage kt-1, now free)
        if (kt + GSTAGES - 1 < NT) {
            const int slot = (kt + GSTAGES - 1) % GSTAGES;
            float* as = As + slot * GSLOT;
            float* bs = Bs + slot * GSLOT;
            const float* ap = Abase + (size_t)(kt + GSTAGES - 1) * 16;
            const float* wp = Wbase + (size_t)(kt + GSTAGES - 1) * 16;
            cp_async16(&as[r0 * 20 + kv], ap);
            cp_async16(&as[(r0 + 64) * 20 + kv], ap + (size_t)64 * K);
            cp_async16(&bs[r0 * 20 + kv], wp);
            cp_async16(&bs[(r0 + 64) * 20 + kv], wp + (size_t)64 * K);
        }
        cp_commit();

        const float* as = As + (kt % GSTAGES) * GSLOT;
        const float* bs = Bs + (kt % GSTAGES) * GSLOT;

#pragma unroll
        for (int k0 = 0; k0 < 16; k0 += 8) {
            uint32_t af[4][4];
#pragma unroll
            for (int mt = 0; mt < 4; mt++) {
                const int row = wm * 64 + mt * 16 + (lane >> 2);
                af[mt][0] = f2tf(as[row * 20 + k0 + (lane & 3)]);
                af[mt][1] = f2tf(as[(row + 8) * 20 + k0 + (lane & 3)]);
                af[mt][2] = f2tf(as[row * 20 + k0 + 4 + (lane & 3)]);
                af[mt][3] = f2tf(as[(row + 8) * 20 + k0 + 4 + (lane & 3)]);
            }
            uint32_t bf[4][2];
#pragma unroll
            for (int nt = 0; nt < 4; nt++) {
                const int col = wn * 32 + nt * 8 + (lane >> 2);
                bf[nt][0] = f2tf(bs[col * 20 + k0 + (lane & 3)]);
                bf[nt][1] = f2tf(bs[col * 20 + k0 + 4 + (lane & 3)]);
            }
#pragma unroll
            for (int mt = 0; mt < 4; mt++)
#pragma unroll
                for (int nt = 0; nt < 4; nt++)
                    mma_tf32(c[mt][nt], af[mt], bf[nt]);
        }
    }

    // epilogue
#pragma unroll
    for (int mt = 0; mt < 4; mt++) {
#pragma unroll
        for (int half = 0; half < 2; half++) {
            const int m = m0 + wm * 64 + mt * 16 + (lane >> 2) + half * 8;
#pragma unroll
            for (int nt = 0; nt < 4; nt++) {
                const int n = n0 + wn * 32 + nt * 8 + 2 * (lane & 3);
                const float v0 = c[mt][nt][2 * half + 0];
                const float v1 = c[mt][nt][2 * half + 1];
                if (REMAP) {
#pragma unroll
                    for (int j = 0; j < 2; j++) {
                        const int nn = n + j;
                        const int t = nn / DD;
                        const int r = nn - t * DD;
                        const int hh = r >> 6;
                        const int e = r & 63;
                        const int bb = m >> 11;
                        const int ss = m & 2047;
                        size_t idx = ((((size_t)t * BB + bb) * HH + hh) * SS + ss) * DKK + e;
                        g_qkv[idx] = j ? v1 : v0;
                    }
                } else {
                    float2 v = make_float2(v0, v1);
                    *(float2*)&C[(size_t)m * N + n] = v;
                }
            }
        }
    }
}

// ---------------------------------------------------------------------------
// Tensor-core causal flash attention. Br=128, Bc=64, dk=64.
// 8 warps; each warp owns 16 full rows -> softmax fully intra-warp.
// Dynamic smem 87040 B -> 2 CTAs/SM; largest-qt-first scheduling.
// ---------------------------------------------------------------------------
__global__ __launch_bounds__(256, 2) void attn_tc() {
    extern __shared__ uint32_t smx[];
    uint32_t* Qs  = smx;                       // [128][68]
    uint32_t* KVs = smx + 128 * 68;            // [64][68]
    uint32_t* Ps  = smx + 128 * 68 + 64 * 68;  // [128][68]

    const int qt = (SS / 128 - 1) - blockIdx.x;   // largest work first
    const int h  = blockIdx.y;
    const int b  = blockIdx.z;
    const int tid  = threadIdx.x;
    const int lane = tid & 31;
    const int wm   = tid >> 5;   // 0..7  -> 16-row slice

    const size_t plane = (size_t)BB * HH * SS * DKK;
    const size_t bh = (size_t)b * HH + h;
    const float* Qg = g_qkv + 0 * plane + bh * SS * DKK;
    const float* Kg = g_qkv + 1 * plane + bh * SS * DKK;
    const float* Vg = g_qkv + 2 * plane + bh * SS * DKK;

    // load Q tile (128 x 64) -> tf32 smem
#pragma unroll
    for (int i = 0; i < 8; i++) {
        const int idx = tid + i * 256;
        const int row = idx >> 4;
        const int c4  = (idx & 15) << 2;
        float4 v = *(const float4*)(Qg + ((size_t)(qt * 128 + row) << 6) + c4);
        uint4 u;
        u.x = f2tf(v.x); u.y = f2tf(v.y); u.z = f2tf(v.z); u.w = f2tf(v.w);
        *(uint4*)&Qs[row * 68 + c4] = u;
    }

    float m_run[2], l_run[2], o[8][4];
    m_run[0] = NEGINF; m_run[1] = NEGINF;
    l_run[0] = 0.0f;   l_run[1] = 0.0f;
#pragma unroll
    for (int nt = 0; nt < 8; nt++)
#pragma unroll
        for (int j = 0; j < 4; j++) o[nt][j] = 0.0f;

    __syncthreads();

    const int ktmax = 2 * qt + 1;
    for (int kt = 0; kt <= ktmax; kt++) {
        // K tile -> KVs
#pragma unroll
        for (int i = 0; i < 4; i++) {
            const int idx = tid + i * 256;
            const int row = idx >> 4;
            const int c4  = (idx & 15) << 2;
            float4 v = *(const float4*)(Kg + ((size_t)(kt * 64 + row) << 6) + c4);
            uint4 u;
            u.x = f2tf(v.x); u.y = f2tf(v.y); u.z = f2tf(v.z); u.w = f2tf(v.w);
            *(uint4*)&KVs[row * 68 + c4] = u;
        }
        __syncthreads();

        // S = Q K^T : warp computes 16 x 64
        float s[8][4];
#pragma unroll
        for (int nt = 0; nt < 8; nt++)
#pragma unroll
            for (int j = 0; j < 4; j++) s[nt][j] = 0.0f;

#pragma unroll
        for (int k0 = 0; k0 < 64; k0 += 8) {
            uint32_t af[4];
            const int row = wm * 16 + (lane >> 2);
            af[0] = Qs[row * 68 + k0 + (lane & 3)];
            af[1] = Qs[(row + 8) * 68 + k0 + (lane & 3)];
            af[2] = Qs[row * 68 + k0 + 4 + (lane & 3)];
            af[3] = Qs[(row + 8) * 68 + k0 + 4 + (lane & 3)];
            uint32_t bf[8][2];
#pragma unroll
            for (int nt = 0; nt < 8; nt++) {
                const int col = nt * 8 + (lane >> 2);
                bf[nt][0] = KVs[col * 68 + k0 + (lane & 3)];
                bf[nt][1] = KVs[col * 68 + k0 + 4 + (lane & 3)];
            }
#pragma unroll
            for (int nt = 0; nt < 8; nt++)
                mma_tf32(s[nt], af, bf[nt]);
        }

        // causal mask (only diagonal-adjacent tiles)
        if (kt >= 2 * qt) {
#pragma unroll
            for (int cc = 0; cc < 4; cc++) {
                const int row_g = qt * 128 + wm * 16 + (lane >> 2) + 8 * (cc >> 1);
#pragma unroll
                for (int nt = 0; nt < 8; nt++) {
                    const int col_g = kt * 64 + nt * 8 + 2 * (lane & 3) + (cc & 1);
                    if (col_g > row_g) s[nt][cc] = NEGINF;
                }
            }
        }

        // online softmax (intra-warp quad reduction)
#pragma unroll
        for (int half = 0; half < 2; half++) {
            float mv = NEGINF;
#pragma unroll
            for (int nt = 0; nt < 8; nt++)
                mv = fmaxf(mv, fmaxf(s[nt][2 * half], s[nt][2 * half + 1]));
            mv = fmaxf(mv, __shfl_xor_sync(0xffffffffu, mv, 1));
            mv = fmaxf(mv, __shfl_xor_sync(0xffffffffu, mv, 2));
            const float mn = fmaxf(m_run[half], mv);
            const float sc = fexp2((m_run[half] - mn) * CEXP);
            m_run[half] = mn;
            float rs = 0.0f;
#pragma unroll
            for (int nt = 0; nt < 8; nt++)
#pragma unroll
                for (int j = 0; j < 2; j++) {
                    float p = fexp2((s[nt][2 * half + j] - mn) * CEXP);
                    s[nt][2 * half + j] = p;
                    rs += p;
                }
            rs += __shfl_xor_sync(0xffffffffu, rs, 1);
            rs += __shfl_xor_sync(0xffffffffu, rs, 2);
            l_run[half] = l_run[half] * sc + rs;
#pragma unroll
            for (int nt = 0; nt < 8; nt++)
#pragma unroll
                for (int j = 0; j < 2; j++) o[nt][2 * half + j] *= sc;
        }

        // write P (tf32) to smem
#pragma unroll
        for (int half = 0; half < 2; half++) {
            const int row = wm * 16 + (lane >> 2) + 8 * half;
#pragma unroll
            for (int nt = 0; nt < 8; nt++) {
                const int col = nt * 8 + 2 * (lane & 3);
                uint2 u;
                u.x = f2tf(s[nt][2 * half]);
                u.y = f2tf(s[nt][2 * half + 1]);
                *(uint2*)&Ps[row * 68 + col] = u;
            }
        }
        __syncthreads();

        // V tile -> KVs
#pragma unroll
        for (int i = 0; i < 4; i++) {
            const int idx = tid + i * 256;
            const int row = idx >> 4;
            const int c4  = (idx & 15) << 2;
            float4 v = *(const float4*)(Vg + ((size_t)(kt * 64 + row) << 6) + c4);
            uint4 u;
            u.x = f2tf(v.x); u.y = f2tf(v.y); u.z = f2tf(v.z); u.w = f2tf(v.w);
            *(uint4*)&KVs[row * 68 + c4] = u;
        }
        __syncthreads();

        // O += P @ V
#pragma unroll
        for (int k0 = 0; k0 < 64; k0 += 8) {
            uint32_t af[4];
            const int row = wm * 16 + (lane >> 2);
            af[0] = Ps[row * 68 + k0 + (lane & 3)];
            af[1] = Ps[(row + 8) * 68 + k0 + (lane & 3)];
            af[2] = Ps[row * 68 + k0 + 4 + (lane & 3)];
            af[3] = Ps[(row + 8) * 68 + k0 + 4 + (lane & 3)];
            uint32_t bf[8][2];
#pragma unroll
            for (int nt = 0; nt < 8; nt++) {
                const int col = nt * 8 + (lane >> 2);
                bf[nt][0] = KVs[(k0 + (lane & 3)) * 68 + col];
                bf[nt][1] = KVs[(k0 + 4 + (lane & 3)) * 68 + col];
            }
#pragma unroll
            for (int nt = 0; nt < 8; nt++)
                mma_tf32(o[nt], af, bf[nt]);
        }
        __syncthreads();
    }

    // epilogue
#pragma unroll
    for (int half = 0; half < 2; half++) {
        const float inv = 1.0f / l_run[half];
        const int row = qt * 128 + wm * 16 + (lane >> 2) + 8 * half;
#pragma unroll
        for (int nt = 0; nt < 8; nt++) {
            const int d = h * 64 + nt * 8 + 2 * (lane & 3);
            float2 v = make_float2(o[nt][2 * half] * inv,
                                   o[nt][2 * half + 1] * inv);
            *(float2*)&g_obuf[((size_t)b * SS + row) * DD + d] = v;
        }
    }
}

#define ATTN_SMEM (320 * 68 * 4)

// ---------------------------------------------------------------------------
extern "C" void kernel_launch(void* const* d_in, const int* in_sizes, int n_in,
                              void* d_out, int out_size) {
    const float* x   = (const float*)d_in[0];  // (4, 2048, 768)
    const float* wqk = (const float*)d_in[1];  // (3, 768, 768)
    const float* wo  = (const float*)d_in[2];  // (768, 768)
    float* out = (float*)d_out;                // (4, 2048, 768)
    (void)in_sizes; (void)n_in; (void)out_size;

    cudaFuncSetAttribute(gemm_tf32<1>, cudaFuncAttributeMaxDynamicSharedMemorySize, GEMM_SMEM);
    cudaFuncSetAttribute(gemm_tf32<0>, cudaFuncAttributeMaxDynamicSharedMemorySize, GEMM_SMEM);
    cudaFuncSetAttribute(attn_tc, cudaFuncAttributeMaxDynamicSharedMemorySize, ATTN_SMEM);

    // 1) QKV projection: (8192 x 768) @ (2304 x 768)^T -> g_qkv (remapped)
    gemm_tf32<1><<<dim3(NQKV / 128, MTOT / 128), 256, GEMM_SMEM>>>(x, wqk, nullptr, MTOT, NQKV, DD);

    // 2) Causal attention -> g_obuf
    attn_tc<<<dim3(SS / 128, HH, BB), 256, ATTN_SMEM>>>();

    // 3) O projection -> out
    float* obuf_ptr;
    cudaGetSymbolAddress((void**)&obuf_ptr, g_obuf);
    gemm_tf32<0><<<dim3(DD / 128, MTOT / 128), 256, GEMM_SMEM>>>(obuf_ptr, wo, out, MTOT, DD, DD);
}